// round 1
// baseline (speedup 1.0000x reference)
#include <cuda_runtime.h>
#include <cstdint>

#define TWO_PI_F 6.28318530717958647692f

namespace {

constexpr int B = 4, S = 4096, V = 64, D = 128;

struct __align__(16) Smem {
    float xs[B][V];        // gathered char embeddings
    float hs[B][V];        // layer-0 output
    float ls[B][D];        // layernorm output (reused by layer 1 and layer 2)
    float h1s[B][D];       // layer-1 output
    float red[2][B][4];    // LN reduction partials (sum, sumsq) x batch x warp
    float ap2[D][D + 1];   // cached P2 * phi128  (stride 129 -> bank-conflict-free)
};

// cos(2*pi*s/p) with exact integer reduction: r = s mod p computed exactly,
// shifted into (-p/2, p/2], then fast cos on a small argument.
__device__ __forceinline__ float phase_cos(float sf, float pf) {
    float rcp = __fdividef(1.0f, pf);
    float q = floorf(sf * rcp);
    float r = fmaf(-q, pf, sf);          // exact: integers < 2^24
    r = (r < 0.0f)  ? (r + pf) : r;      // fix potential off-by-one in q
    r = (r >= pf)   ? (r - pf) : r;
    r = ((r + r) > pf) ? (r - pf) : r;   // shift to (-p/2, p/2]
    return __cosf(TWO_PI_F * r * rcp);
}

} // namespace

extern "C" __global__ void __launch_bounds__(128)
hier_kernel(const int* __restrict__ tokens, const int* __restrict__ positions,
            const float* __restrict__ emb, const float* __restrict__ charP,
            const float* __restrict__ M1, const float* __restrict__ P1,
            const float* __restrict__ g1, const float* __restrict__ b1v,
            const float* __restrict__ R1, const float* __restrict__ M2,
            const float* __restrict__ P2, const float* __restrict__ g2,
            const float* __restrict__ b2v, float* __restrict__ out)
{
    extern __shared__ Smem smem_raw[];
    Smem& sm = smem_raw[0];

    const int sidx = blockIdx.x;
    const int tid  = (int)threadIdx.x;
    const int lane = tid & 31;
    const int wid  = tid >> 5;
    const float sf = (float)positions[sidx];

    // ---- gather char embeddings for all 4 batches -------------------------
    {
        int tk[B];
        #pragma unroll
        for (int b = 0; b < B; ++b) tk[b] = tokens[b * S + sidx];
        #pragma unroll
        for (int k = 0; k < 2; ++k) {
            int idx = tid + k * 128;
            int b = idx >> 6, j = idx & 63;
            sm.xs[b][j] = emb[tk[b] * V + j];
        }
    }
    __syncthreads();

    // ---- layer 0: h = (char_P .* phi64) @ x  ------------------------------
    // threads 0..63 -> row i, batches 0,1 ; threads 64..127 -> row i, batches 2,3
    {
        const int i  = tid & 63;
        const int bb = (tid >> 6) << 1;
        const float4* cp4 = reinterpret_cast<const float4*>(charP + i * V);
        const float4* x0  = reinterpret_cast<const float4*>(sm.xs[bb]);
        const float4* x1  = reinterpret_cast<const float4*>(sm.xs[bb + 1]);
        float a0 = 0.f, a1 = 0.f;
        const float pbase = (float)(i * V + 2);
        #pragma unroll 4
        for (int j4 = 0; j4 < V / 4; ++j4) {
            float4 w = cp4[j4];
            float pj = pbase + (float)(4 * j4);
            float e0 = w.x * phase_cos(sf, pj);
            float e1 = w.y * phase_cos(sf, pj + 1.f);
            float e2 = w.z * phase_cos(sf, pj + 2.f);
            float e3 = w.w * phase_cos(sf, pj + 3.f);
            float4 xa = x0[j4];
            float4 xb = x1[j4];
            a0 = fmaf(e0, xa.x, fmaf(e1, xa.y, fmaf(e2, xa.z, fmaf(e3, xa.w, a0))));
            a1 = fmaf(e0, xb.x, fmaf(e1, xb.y, fmaf(e2, xb.z, fmaf(e3, xb.w, a1))));
        }
        sm.hs[bb][i]     = a0;
        sm.hs[bb + 1][i] = a1;
    }
    __syncthreads();

    const int i = tid;   // output row owned by this thread (layers 1 & 2)

    // layernorm over the 128 rows (thread dim); tv[b] is this thread's element.
    auto layernorm = [&](float (&tv)[B], const float* gg, const float* bb) {
        float s1[B], s2[B];
        #pragma unroll
        for (int b = 0; b < B; ++b) { s1[b] = tv[b]; s2[b] = tv[b] * tv[b]; }
        #pragma unroll
        for (int o = 16; o; o >>= 1) {
            #pragma unroll
            for (int b = 0; b < B; ++b) {
                s1[b] += __shfl_xor_sync(0xffffffffu, s1[b], o);
                s2[b] += __shfl_xor_sync(0xffffffffu, s2[b], o);
            }
        }
        if (lane == 0) {
            #pragma unroll
            for (int b = 0; b < B; ++b) {
                sm.red[0][b][wid] = s1[b];
                sm.red[1][b][wid] = s2[b];
            }
        }
        __syncthreads();
        const float gi = gg[i], bi = bb[i];
        #pragma unroll
        for (int b = 0; b < B; ++b) {
            float su = sm.red[0][b][0] + sm.red[0][b][1] + sm.red[0][b][2] + sm.red[0][b][3];
            float sq = sm.red[1][b][0] + sm.red[1][b][1] + sm.red[1][b][2] + sm.red[1][b][3];
            float mu  = su * (1.0f / D);
            float var = fmaf(sq, 1.0f / D, -mu * mu);
            float rs  = rsqrtf(var + 1e-5f);
            sm.ls[b][i] = fmaf((tv[b] - mu) * rs, gi, bi);
        }
        __syncthreads();
    };

    // ---- layer 1: t1 = M1 @ h --------------------------------------------
    float t1v[B] = {0.f, 0.f, 0.f, 0.f};
    {
        const float4* m1 = reinterpret_cast<const float4*>(M1 + i * V);
        #pragma unroll
        for (int j4 = 0; j4 < V / 4; ++j4) {
            float4 w = m1[j4];
            #pragma unroll
            for (int b = 0; b < B; ++b) {
                float4 x = reinterpret_cast<const float4*>(sm.hs[b])[j4];
                t1v[b] = fmaf(w.x, x.x, fmaf(w.y, x.y, fmaf(w.z, x.z, fmaf(w.w, x.w, t1v[b]))));
            }
        }
    }
    layernorm(t1v, g1, b1v);

    // ---- layer 1 pos_nk + cache P2*phi + residual R1 @ h ------------------
    float h1v[B] = {0.f, 0.f, 0.f, 0.f};
    {
        const float4* p1r = reinterpret_cast<const float4*>(P1 + i * D);
        const float4* p2r = reinterpret_cast<const float4*>(P2 + i * D);
        float* ap2row = sm.ap2[i];
        const float pbase = (float)(i * D + 2);
        #pragma unroll 4
        for (int j4 = 0; j4 < D / 4; ++j4) {
            float4 w1 = p1r[j4];
            float4 w2 = p2r[j4];
            float pj = pbase + (float)(4 * j4);
            float ph0 = phase_cos(sf, pj);
            float ph1 = phase_cos(sf, pj + 1.f);
            float ph2 = phase_cos(sf, pj + 2.f);
            float ph3 = phase_cos(sf, pj + 3.f);
            float a0 = w1.x * ph0, a1 = w1.y * ph1, a2 = w1.z * ph2, a3 = w1.w * ph3;
            ap2row[4 * j4 + 0] = w2.x * ph0;
            ap2row[4 * j4 + 1] = w2.y * ph1;
            ap2row[4 * j4 + 2] = w2.z * ph2;
            ap2row[4 * j4 + 3] = w2.w * ph3;
            #pragma unroll
            for (int b = 0; b < B; ++b) {
                float4 x = reinterpret_cast<const float4*>(sm.ls[b])[j4];
                h1v[b] = fmaf(a0, x.x, fmaf(a1, x.y, fmaf(a2, x.z, fmaf(a3, x.w, h1v[b]))));
            }
        }
        // residual: + R1 @ h
        const float4* r1 = reinterpret_cast<const float4*>(R1 + i * V);
        #pragma unroll
        for (int j4 = 0; j4 < V / 4; ++j4) {
            float4 w = r1[j4];
            #pragma unroll
            for (int b = 0; b < B; ++b) {
                float4 x = reinterpret_cast<const float4*>(sm.hs[b])[j4];
                h1v[b] = fmaf(w.x, x.x, fmaf(w.y, x.y, fmaf(w.z, x.z, fmaf(w.w, x.w, h1v[b]))));
            }
        }
        #pragma unroll
        for (int b = 0; b < B; ++b) sm.h1s[b][i] = h1v[b];
    }
    __syncthreads();

    // ---- layer 2: t2 = M2 @ h1 -------------------------------------------
    float t2v[B] = {0.f, 0.f, 0.f, 0.f};
    {
        const float4* m2 = reinterpret_cast<const float4*>(M2 + i * D);
        #pragma unroll 8
        for (int j4 = 0; j4 < D / 4; ++j4) {
            float4 w = m2[j4];
            #pragma unroll
            for (int b = 0; b < B; ++b) {
                float4 x = reinterpret_cast<const float4*>(sm.h1s[b])[j4];
                t2v[b] = fmaf(w.x, x.x, fmaf(w.y, x.y, fmaf(w.z, x.z, fmaf(w.w, x.w, t2v[b]))));
            }
        }
    }
    layernorm(t2v, g2, b2v);

    // ---- layer 2 pos_nk using cached P2*phi, plus shared residual t2 ------
    float ov[B] = {0.f, 0.f, 0.f, 0.f};
    {
        const float* ap2row = sm.ap2[i];
        #pragma unroll 8
        for (int j4 = 0; j4 < D / 4; ++j4) {
            float a0 = ap2row[4 * j4 + 0];
            float a1 = ap2row[4 * j4 + 1];
            float a2 = ap2row[4 * j4 + 2];
            float a3 = ap2row[4 * j4 + 3];
            #pragma unroll
            for (int b = 0; b < B; ++b) {
                float4 x = reinterpret_cast<const float4*>(sm.ls[b])[j4];
                ov[b] = fmaf(a0, x.x, fmaf(a1, x.y, fmaf(a2, x.z, fmaf(a3, x.w, ov[b]))));
            }
        }
    }
    #pragma unroll
    for (int b = 0; b < B; ++b)
        out[(b * S + sidx) * D + i] = ov[b] + t2v[b];
}

extern "C" void kernel_launch(void* const* d_in, const int* in_sizes, int n_in,
                              void* d_out, int out_size) {
    const int*   tokens    = (const int*)d_in[0];
    const int*   positions = (const int*)d_in[1];
    const float* emb       = (const float*)d_in[2];
    const float* charP     = (const float*)d_in[3];
    const float* M1        = (const float*)d_in[4];
    const float* P1        = (const float*)d_in[5];
    const float* g1        = (const float*)d_in[6];
    const float* b1        = (const float*)d_in[7];
    const float* R1        = (const float*)d_in[8];
    const float* M2        = (const float*)d_in[9];
    const float* P2        = (const float*)d_in[10];
    const float* g2        = (const float*)d_in[11];
    const float* b2        = (const float*)d_in[12];
    float* out = (float*)d_out;

    cudaFuncSetAttribute(hier_kernel, cudaFuncAttributeMaxDynamicSharedMemorySize,
                         (int)sizeof(Smem));
    hier_kernel<<<S, 128, (int)sizeof(Smem)>>>(
        tokens, positions, emb, charP, M1, P1, g1, b1, R1, M2, P2, g2, b2, out);
}

// round 3
// speedup vs baseline: 1.0702x; 1.0702x over previous
#include <cuda_runtime.h>
#include <cstdint>

#define TWO_PI_F 6.28318530717958647692f

namespace {

constexpr int B = 4, S = 4096, V = 64, D = 128;

struct __align__(16) Smem {
    float xs[B][V];        // gathered char embeddings
    float hs[B][V];        // layer-0 output
    float ls[B][D];        // layernorm output (reused by layer 1 and layer 2)
    float h1s[B][D];       // layer-1 output
    float red[2][B][4];    // LN reduction partials
    float ap2[D][D];       // cached P2*phi, layout [j][i]  (coalesced scalar access)
};

// cos(2*pi*s/p) with exact integer range reduction.
__device__ __forceinline__ float phase_cos(float sf, float pf) {
    float rcp = __fdividef(1.0f, pf);
    float q = floorf(sf * rcp);
    float r = fmaf(-q, pf, sf);
    r = (r < 0.0f)  ? (r + pf) : r;
    r = (r >= pf)   ? (r - pf) : r;
    r = ((r + r) > pf) ? (r - pf) : r;
    return __cosf(TWO_PI_F * r * rcp);
}

} // namespace

// ---- transposed weight scratch (position-invariant, rebuilt every launch) --
__device__ float g_charPT[V * V];   // [j][i]
__device__ float g_M1T[V * D];      // [j][i]
__device__ float g_R1T[V * D];      // [j][i]
__device__ float g_P1T[D * D];      // [j][i]
__device__ float g_P2T[D * D];      // [j][i]
__device__ float g_M2T[D * D];      // [j][i]

extern "C" __global__ void __launch_bounds__(256)
transpose_weights(const float* __restrict__ charP, const float* __restrict__ M1,
                  const float* __restrict__ R1,    const float* __restrict__ P1,
                  const float* __restrict__ P2,    const float* __restrict__ M2)
{
    int t = blockIdx.x * blockDim.x + threadIdx.x;
    if (t < 4096) {                       // charP: 64x64
        int i = t >> 6, j = t & 63;
        g_charPT[j * V + i] = charP[t];
    } else if (t < 12288) {               // M1: 128x64
        int u = t - 4096; int i = u >> 6, j = u & 63;
        g_M1T[j * D + i] = M1[u];
    } else if (t < 20480) {               // R1: 128x64
        int u = t - 12288; int i = u >> 6, j = u & 63;
        g_R1T[j * D + i] = R1[u];
    } else if (t < 36864) {               // P1: 128x128
        int u = t - 20480; int i = u >> 7, j = u & 127;
        g_P1T[j * D + i] = P1[u];
    } else if (t < 53248) {               // P2: 128x128
        int u = t - 36864; int i = u >> 7, j = u & 127;
        g_P2T[j * D + i] = P2[u];
    } else if (t < 69632) {               // M2: 128x128
        int u = t - 53248; int i = u >> 7, j = u & 127;
        g_M2T[j * D + i] = M2[u];
    }
}

extern "C" __global__ void __launch_bounds__(128)
hier_kernel(const int* __restrict__ tokens, const int* __restrict__ positions,
            const float* __restrict__ emb,
            const float* __restrict__ g1, const float* __restrict__ b1v,
            const float* __restrict__ g2, const float* __restrict__ b2v,
            float* __restrict__ out)
{
    extern __shared__ Smem smem_raw[];
    Smem& sm = smem_raw[0];

    const int sidx = blockIdx.x;
    const int tid  = (int)threadIdx.x;
    const int lane = tid & 31;
    const int wid  = tid >> 5;
    const float sf = (float)positions[sidx];

    // ---- gather char embeddings for all 4 batches -------------------------
    {
        int tk[B];
        #pragma unroll
        for (int b = 0; b < B; ++b) tk[b] = tokens[b * S + sidx];
        #pragma unroll
        for (int k = 0; k < 2; ++k) {
            int idx = tid + k * 128;
            int b = idx >> 6, j = idx & 63;
            sm.xs[b][j] = emb[tk[b] * V + j];
        }
    }
    __syncthreads();

    // ---- layer 0: h = (char_P .* phi64) @ x  ------------------------------
    // thread: i = tid&63 ; half 0 -> batches 0,1 ; half 1 -> batches 2,3
    {
        const int i  = tid & 63;
        const int bb = (tid >> 6) << 1;
        const float4* x0 = reinterpret_cast<const float4*>(sm.xs[bb]);
        const float4* x1 = reinterpret_cast<const float4*>(sm.xs[bb + 1]);
        float a0 = 0.f, a1 = 0.f;
        const float pbase = (float)(i * V + 2);
        #pragma unroll 4
        for (int j4 = 0; j4 < V / 4; ++j4) {
            float4 xa = x0[j4];
            float4 xb = x1[j4];
            #pragma unroll
            for (int e = 0; e < 4; ++e) {
                int j = 4 * j4 + e;
                float w  = g_charPT[j * V + i];                 // coalesced LDG
                float wp = w * phase_cos(sf, pbase + (float)j);
                float xe0 = (e == 0) ? xa.x : (e == 1) ? xa.y : (e == 2) ? xa.z : xa.w;
                float xe1 = (e == 0) ? xb.x : (e == 1) ? xb.y : (e == 2) ? xb.z : xb.w;
                a0 = fmaf(wp, xe0, a0);
                a1 = fmaf(wp, xe1, a1);
            }
        }
        sm.hs[bb][i]     = a0;
        sm.hs[bb + 1][i] = a1;
    }
    __syncthreads();

    const int i = tid;   // output row owned by this thread in layers 1 & 2

    auto layernorm = [&](float (&tv)[B], const float* gg, const float* bb) {
        float s1[B], s2[B];
        #pragma unroll
        for (int b = 0; b < B; ++b) { s1[b] = tv[b]; s2[b] = tv[b] * tv[b]; }
        #pragma unroll
        for (int o = 16; o; o >>= 1) {
            #pragma unroll
            for (int b = 0; b < B; ++b) {
                s1[b] += __shfl_xor_sync(0xffffffffu, s1[b], o);
                s2[b] += __shfl_xor_sync(0xffffffffu, s2[b], o);
            }
        }
        if (lane == 0) {
            #pragma unroll
            for (int b = 0; b < B; ++b) {
                sm.red[0][b][wid] = s1[b];
                sm.red[1][b][wid] = s2[b];
            }
        }
        __syncthreads();
        const float gi = gg[i], bi = bb[i];
        #pragma unroll
        for (int b = 0; b < B; ++b) {
            float su = sm.red[0][b][0] + sm.red[0][b][1] + sm.red[0][b][2] + sm.red[0][b][3];
            float sq = sm.red[1][b][0] + sm.red[1][b][1] + sm.red[1][b][2] + sm.red[1][b][3];
            float mu  = su * (1.0f / D);
            float var = fmaf(sq, 1.0f / D, -mu * mu);
            float rs  = rsqrtf(var + 1e-5f);
            sm.ls[b][i] = fmaf((tv[b] - mu) * rs, gi, bi);
        }
        __syncthreads();
    };

    // ---- layer 1: t1 = M1 @ h  (coalesced M1T reads) ----------------------
    float t1v[B] = {0.f, 0.f, 0.f, 0.f};
    {
        #pragma unroll 4
        for (int j4 = 0; j4 < V / 4; ++j4) {
            float4 xb[B];
            #pragma unroll
            for (int b = 0; b < B; ++b)
                xb[b] = reinterpret_cast<const float4*>(sm.hs[b])[j4];
            #pragma unroll
            for (int e = 0; e < 4; ++e) {
                int j = 4 * j4 + e;
                float w = g_M1T[j * D + i];
                #pragma unroll
                for (int b = 0; b < B; ++b) {
                    float xe = (e == 0) ? xb[b].x : (e == 1) ? xb[b].y : (e == 2) ? xb[b].z : xb[b].w;
                    t1v[b] = fmaf(w, xe, t1v[b]);
                }
            }
        }
    }
    layernorm(t1v, g1, b1v);

    // ---- layer 1 pos_nk + cache P2*phi + residual R1 @ h ------------------
    float h1v[B] = {0.f, 0.f, 0.f, 0.f};
    {
        const float pbase = (float)(i * D + 2);
        #pragma unroll 4
        for (int j4 = 0; j4 < D / 4; ++j4) {
            float4 xb[B];
            #pragma unroll
            for (int b = 0; b < B; ++b)
                xb[b] = reinterpret_cast<const float4*>(sm.ls[b])[j4];
            #pragma unroll
            for (int e = 0; e < 4; ++e) {
                int j = 4 * j4 + e;
                float w1 = g_P1T[j * D + i];
                float w2 = g_P2T[j * D + i];
                float ph = phase_cos(sf, pbase + (float)j);
                float a1 = w1 * ph;
                sm.ap2[j][i] = w2 * ph;                          // coalesced STS
                #pragma unroll
                for (int b = 0; b < B; ++b) {
                    float xe = (e == 0) ? xb[b].x : (e == 1) ? xb[b].y : (e == 2) ? xb[b].z : xb[b].w;
                    h1v[b] = fmaf(a1, xe, h1v[b]);
                }
            }
        }
        // residual: + R1 @ h
        #pragma unroll 4
        for (int j4 = 0; j4 < V / 4; ++j4) {
            float4 xb[B];
            #pragma unroll
            for (int b = 0; b < B; ++b)
                xb[b] = reinterpret_cast<const float4*>(sm.hs[b])[j4];
            #pragma unroll
            for (int e = 0; e < 4; ++e) {
                int j = 4 * j4 + e;
                float w = g_R1T[j * D + i];
                #pragma unroll
                for (int b = 0; b < B; ++b) {
                    float xe = (e == 0) ? xb[b].x : (e == 1) ? xb[b].y : (e == 2) ? xb[b].z : xb[b].w;
                    h1v[b] = fmaf(w, xe, h1v[b]);
                }
            }
        }
        #pragma unroll
        for (int b = 0; b < B; ++b) sm.h1s[b][i] = h1v[b];
    }
    __syncthreads();

    // ---- layer 2: t2 = M2 @ h1 -------------------------------------------
    float t2v[B] = {0.f, 0.f, 0.f, 0.f};
    {
        #pragma unroll 4
        for (int j4 = 0; j4 < D / 4; ++j4) {
            float4 xb[B];
            #pragma unroll
            for (int b = 0; b < B; ++b)
                xb[b] = reinterpret_cast<const float4*>(sm.h1s[b])[j4];
            #pragma unroll
            for (int e = 0; e < 4; ++e) {
                int j = 4 * j4 + e;
                float w = g_M2T[j * D + i];
                #pragma unroll
                for (int b = 0; b < B; ++b) {
                    float xe = (e == 0) ? xb[b].x : (e == 1) ? xb[b].y : (e == 2) ? xb[b].z : xb[b].w;
                    t2v[b] = fmaf(w, xe, t2v[b]);
                }
            }
        }
    }
    layernorm(t2v, g2, b2v);

    // ---- layer 2 pos_nk via cached P2*phi + shared residual t2 ------------
    float ov[B] = {0.f, 0.f, 0.f, 0.f};
    {
        #pragma unroll 4
        for (int j4 = 0; j4 < D / 4; ++j4) {
            float4 xb[B];
            #pragma unroll
            for (int b = 0; b < B; ++b)
                xb[b] = reinterpret_cast<const float4*>(sm.ls[b])[j4];
            #pragma unroll
            for (int e = 0; e < 4; ++e) {
                int j = 4 * j4 + e;
                float a = sm.ap2[j][i];                          // coalesced LDS
                #pragma unroll
                for (int b = 0; b < B; ++b) {
                    float xe = (e == 0) ? xb[b].x : (e == 1) ? xb[b].y : (e == 2) ? xb[b].z : xb[b].w;
                    ov[b] = fmaf(a, xe, ov[b]);
                }
            }
        }
    }
    #pragma unroll
    for (int b = 0; b < B; ++b)
        out[(b * S + sidx) * D + i] = ov[b] + t2v[b];
}

extern "C" void kernel_launch(void* const* d_in, const int* in_sizes, int n_in,
                              void* d_out, int out_size) {
    const int*   tokens    = (const int*)d_in[0];
    const int*   positions = (const int*)d_in[1];
    const float* emb       = (const float*)d_in[2];
    const float* charP     = (const float*)d_in[3];
    const float* M1        = (const float*)d_in[4];
    const float* P1        = (const float*)d_in[5];
    const float* g1        = (const float*)d_in[6];
    const float* b1        = (const float*)d_in[7];
    const float* R1        = (const float*)d_in[8];
    const float* M2        = (const float*)d_in[9];
    const float* P2        = (const float*)d_in[10];
    const float* g2        = (const float*)d_in[11];
    const float* b2        = (const float*)d_in[12];
    float* out = (float*)d_out;

    transpose_weights<<<(69632 + 255) / 256, 256>>>(charP, M1, R1, P1, P2, M2);

    cudaFuncSetAttribute(hier_kernel, cudaFuncAttributeMaxDynamicSharedMemorySize,
                         (int)sizeof(Smem));
    hier_kernel<<<S, 128, (int)sizeof(Smem)>>>(
        tokens, positions, emb, g1, b1, g2, b2, out);
}

// round 4
// speedup vs baseline: 1.8627x; 1.7405x over previous
#include <cuda_runtime.h>
#include <cstdint>

#define TWO_PI_F 6.28318530717958647692f

namespace {

constexpr int B = 4, S = 4096, V = 64, D = 128;

struct __align__(16) Smem {
    float xs[B][V];        // gathered char embeddings
    float hs[B][V];        // layer-0 output
    float ls[B][D];        // layernorm output (reused by layer 1 and layer 2)
    float h1s[B][D];       // layer-1 output
    float red[2][B][4];    // LN reduction partials
};

// cos(2*pi*s/p) with exact integer range reduction.
__device__ __forceinline__ float phase_cos(float sf, float pf) {
    float rcp = __fdividef(1.0f, pf);
    float q = floorf(sf * rcp);
    float r = fmaf(-q, pf, sf);
    r = (r < 0.0f)  ? (r + pf) : r;
    r = (r >= pf)   ? (r - pf) : r;
    r = ((r + r) > pf) ? (r - pf) : r;
    return __cosf(TWO_PI_F * r * rcp);
}

} // namespace

// ---- transposed weight scratch (position-invariant, rebuilt every launch) --
__device__ float g_charPT[V * V];   // [j][i]
__device__ float g_M1T[V * D];      // [j][i]
__device__ float g_R1T[V * D];      // [j][i]
__device__ float g_P1T[D * D];      // [j][i]
__device__ float g_P2T[D * D];      // [j][i]
__device__ float g_M2T[D * D];      // [j][i]

extern "C" __global__ void __launch_bounds__(256)
transpose_weights(const float* __restrict__ charP, const float* __restrict__ M1,
                  const float* __restrict__ R1,    const float* __restrict__ P1,
                  const float* __restrict__ P2,    const float* __restrict__ M2)
{
    int t = blockIdx.x * blockDim.x + threadIdx.x;
    if (t < 4096) {                       // charP: 64x64
        int i = t >> 6, j = t & 63;
        g_charPT[j * V + i] = charP[t];
    } else if (t < 12288) {               // M1: 128x64
        int u = t - 4096; int i = u >> 6, j = u & 63;
        g_M1T[j * D + i] = M1[u];
    } else if (t < 20480) {               // R1: 128x64
        int u = t - 12288; int i = u >> 6, j = u & 63;
        g_R1T[j * D + i] = R1[u];
    } else if (t < 36864) {               // P1: 128x128
        int u = t - 20480; int i = u >> 7, j = u & 127;
        g_P1T[j * D + i] = P1[u];
    } else if (t < 53248) {               // P2: 128x128
        int u = t - 36864; int i = u >> 7, j = u & 127;
        g_P2T[j * D + i] = P2[u];
    } else if (t < 69632) {               // M2: 128x128
        int u = t - 53248; int i = u >> 7, j = u & 127;
        g_M2T[j * D + i] = M2[u];
    }
}

extern "C" __global__ void __launch_bounds__(128)
hier_kernel(const int* __restrict__ tokens, const int* __restrict__ positions,
            const float* __restrict__ emb,
            const float* __restrict__ g1, const float* __restrict__ b1v,
            const float* __restrict__ g2, const float* __restrict__ b2v,
            float* __restrict__ out)
{
    __shared__ Smem sm;

    const int sidx = blockIdx.x;
    const int tid  = (int)threadIdx.x;
    const int lane = tid & 31;
    const int wid  = tid >> 5;
    const float sf = (float)positions[sidx];

    // ---- gather char embeddings for all 4 batches -------------------------
    {
        int tk[B];
        #pragma unroll
        for (int b = 0; b < B; ++b) tk[b] = tokens[b * S + sidx];
        #pragma unroll
        for (int k = 0; k < 2; ++k) {
            int idx = tid + k * 128;
            int b = idx >> 6, j = idx & 63;
            sm.xs[b][j] = emb[tk[b] * V + j];
        }
    }
    __syncthreads();

    // ---- layer 0: h = (char_P .* phi64) @ x  ------------------------------
    // thread: i = tid&63 ; half 0 -> batches 0,1 ; half 1 -> batches 2,3
    {
        const int i  = tid & 63;
        const int bb = (tid >> 6) << 1;
        const float4* x0 = reinterpret_cast<const float4*>(sm.xs[bb]);
        const float4* x1 = reinterpret_cast<const float4*>(sm.xs[bb + 1]);
        float a0 = 0.f, a1 = 0.f;
        const float pbase = (float)(i * V + 2);
        #pragma unroll 4
        for (int j4 = 0; j4 < V / 4; ++j4) {
            float4 xa = x0[j4];
            float4 xb = x1[j4];
            #pragma unroll
            for (int e = 0; e < 4; ++e) {
                int j = 4 * j4 + e;
                float w  = g_charPT[j * V + i];                 // coalesced LDG
                float wp = w * phase_cos(sf, pbase + (float)j);
                float xe0 = (e == 0) ? xa.x : (e == 1) ? xa.y : (e == 2) ? xa.z : xa.w;
                float xe1 = (e == 0) ? xb.x : (e == 1) ? xb.y : (e == 2) ? xb.z : xb.w;
                a0 = fmaf(wp, xe0, a0);
                a1 = fmaf(wp, xe1, a1);
            }
        }
        sm.hs[bb][i]     = a0;
        sm.hs[bb + 1][i] = a1;
    }
    __syncthreads();

    const int i = tid;   // output row owned by this thread in layers 1 & 2

    auto layernorm = [&](float (&tv)[B], const float* gg, const float* bb) {
        float s1[B], s2[B];
        #pragma unroll
        for (int b = 0; b < B; ++b) { s1[b] = tv[b]; s2[b] = tv[b] * tv[b]; }
        #pragma unroll
        for (int o = 16; o; o >>= 1) {
            #pragma unroll
            for (int b = 0; b < B; ++b) {
                s1[b] += __shfl_xor_sync(0xffffffffu, s1[b], o);
                s2[b] += __shfl_xor_sync(0xffffffffu, s2[b], o);
            }
        }
        if (lane == 0) {
            #pragma unroll
            for (int b = 0; b < B; ++b) {
                sm.red[0][b][wid] = s1[b];
                sm.red[1][b][wid] = s2[b];
            }
        }
        __syncthreads();
        const float gi = gg[i], bi = bb[i];
        #pragma unroll
        for (int b = 0; b < B; ++b) {
            float su = sm.red[0][b][0] + sm.red[0][b][1] + sm.red[0][b][2] + sm.red[0][b][3];
            float sq = sm.red[1][b][0] + sm.red[1][b][1] + sm.red[1][b][2] + sm.red[1][b][3];
            float mu  = su * (1.0f / D);
            float var = fmaf(sq, 1.0f / D, -mu * mu);
            float rs  = rsqrtf(var + 1e-5f);
            sm.ls[b][i] = fmaf((tv[b] - mu) * rs, gi, bi);
        }
        __syncthreads();
    };

    // ---- layer 1: t1 = M1 @ h  (coalesced M1T reads) ----------------------
    float t1v[B] = {0.f, 0.f, 0.f, 0.f};
    {
        #pragma unroll 4
        for (int j4 = 0; j4 < V / 4; ++j4) {
            float4 xb[B];
            #pragma unroll
            for (int b = 0; b < B; ++b)
                xb[b] = reinterpret_cast<const float4*>(sm.hs[b])[j4];
            #pragma unroll
            for (int e = 0; e < 4; ++e) {
                int j = 4 * j4 + e;
                float w = g_M1T[j * D + i];
                #pragma unroll
                for (int b = 0; b < B; ++b) {
                    float xe = (e == 0) ? xb[b].x : (e == 1) ? xb[b].y : (e == 2) ? xb[b].z : xb[b].w;
                    t1v[b] = fmaf(w, xe, t1v[b]);
                }
            }
        }
    }
    layernorm(t1v, g1, b1v);

    // ---- layer 1 pos_nk + residual R1 @ h ---------------------------------
    const float pbase = (float)(i * D + 2);
    float h1v[B] = {0.f, 0.f, 0.f, 0.f};
    {
        #pragma unroll 4
        for (int j4 = 0; j4 < D / 4; ++j4) {
            float4 xb[B];
            #pragma unroll
            for (int b = 0; b < B; ++b)
                xb[b] = reinterpret_cast<const float4*>(sm.ls[b])[j4];
            #pragma unroll
            for (int e = 0; e < 4; ++e) {
                int j = 4 * j4 + e;
                float w1 = g_P1T[j * D + i];
                float a1 = w1 * phase_cos(sf, pbase + (float)j);
                #pragma unroll
                for (int b = 0; b < B; ++b) {
                    float xe = (e == 0) ? xb[b].x : (e == 1) ? xb[b].y : (e == 2) ? xb[b].z : xb[b].w;
                    h1v[b] = fmaf(a1, xe, h1v[b]);
                }
            }
        }
        // residual: + R1 @ h
        #pragma unroll 4
        for (int j4 = 0; j4 < V / 4; ++j4) {
            float4 xb[B];
            #pragma unroll
            for (int b = 0; b < B; ++b)
                xb[b] = reinterpret_cast<const float4*>(sm.hs[b])[j4];
            #pragma unroll
            for (int e = 0; e < 4; ++e) {
                int j = 4 * j4 + e;
                float w = g_R1T[j * D + i];
                #pragma unroll
                for (int b = 0; b < B; ++b) {
                    float xe = (e == 0) ? xb[b].x : (e == 1) ? xb[b].y : (e == 2) ? xb[b].z : xb[b].w;
                    h1v[b] = fmaf(w, xe, h1v[b]);
                }
            }
        }
        #pragma unroll
        for (int b = 0; b < B; ++b) sm.h1s[b][i] = h1v[b];
    }
    __syncthreads();

    // ---- layer 2: t2 = M2 @ h1 -------------------------------------------
    float t2v[B] = {0.f, 0.f, 0.f, 0.f};
    {
        #pragma unroll 4
        for (int j4 = 0; j4 < D / 4; ++j4) {
            float4 xb[B];
            #pragma unroll
            for (int b = 0; b < B; ++b)
                xb[b] = reinterpret_cast<const float4*>(sm.h1s[b])[j4];
            #pragma unroll
            for (int e = 0; e < 4; ++e) {
                int j = 4 * j4 + e;
                float w = g_M2T[j * D + i];
                #pragma unroll
                for (int b = 0; b < B; ++b) {
                    float xe = (e == 0) ? xb[b].x : (e == 1) ? xb[b].y : (e == 2) ? xb[b].z : xb[b].w;
                    t2v[b] = fmaf(w, xe, t2v[b]);
                }
            }
        }
    }
    layernorm(t2v, g2, b2v);

    // ---- layer 2 pos_nk (recompute P2*phi) + shared residual t2 -----------
    float ov[B] = {0.f, 0.f, 0.f, 0.f};
    {
        #pragma unroll 4
        for (int j4 = 0; j4 < D / 4; ++j4) {
            float4 xb[B];
            #pragma unroll
            for (int b = 0; b < B; ++b)
                xb[b] = reinterpret_cast<const float4*>(sm.ls[b])[j4];
            #pragma unroll
            for (int e = 0; e < 4; ++e) {
                int j = 4 * j4 + e;
                float w2 = g_P2T[j * D + i];
                float a  = w2 * phase_cos(sf, pbase + (float)j);
                #pragma unroll
                for (int b = 0; b < B; ++b) {
                    float xe = (e == 0) ? xb[b].x : (e == 1) ? xb[b].y : (e == 2) ? xb[b].z : xb[b].w;
                    ov[b] = fmaf(a, xe, ov[b]);
                }
            }
        }
    }
    #pragma unroll
    for (int b = 0; b < B; ++b)
        out[(b * S + sidx) * D + i] = ov[b] + t2v[b];
}

extern "C" void kernel_launch(void* const* d_in, const int* in_sizes, int n_in,
                              void* d_out, int out_size) {
    const int*   tokens    = (const int*)d_in[0];
    const int*   positions = (const int*)d_in[1];
    const float* emb       = (const float*)d_in[2];
    const float* charP     = (const float*)d_in[3];
    const float* M1        = (const float*)d_in[4];
    const float* P1        = (const float*)d_in[5];
    const float* g1        = (const float*)d_in[6];
    const float* b1        = (const float*)d_in[7];
    const float* R1        = (const float*)d_in[8];
    const float* M2        = (const float*)d_in[9];
    const float* P2        = (const float*)d_in[10];
    const float* g2        = (const float*)d_in[11];
    const float* b2        = (const float*)d_in[12];
    float* out = (float*)d_out;

    transpose_weights<<<(69632 + 255) / 256, 256>>>(charP, M1, R1, P1, P2, M2);

    hier_kernel<<<S, 128>>>(tokens, positions, emb, g1, b1, g2, b2, out);
}

// round 5
// speedup vs baseline: 2.6531x; 1.4243x over previous
#include <cuda_runtime.h>
#include <cstdint>

#define TWO_PI_F 6.28318530717958647692f

namespace {

constexpr int B = 4, S = 4096, V = 64, D = 128;

struct __align__(16) Smem {
    float xs2[2][V][2];    // [pair][j][half]  pair p = batches (2p, 2p+1)
    float hs2[2][V][2];
    float ls2[2][D][2];
    float h1s2[2][D][2];
    float red[2][B][4];
};

// ---- f32x2 packed helpers --------------------------------------------------
__device__ __forceinline__ unsigned long long dup2(float a) {
    unsigned long long r; unsigned int u = __float_as_uint(a);
    asm("mov.b64 %0, {%1, %1};" : "=l"(r) : "r"(u));
    return r;
}
__device__ __forceinline__ unsigned long long pk2(float a, float b) {
    unsigned long long r;
    asm("mov.b64 %0, {%1, %2};" : "=l"(r) : "r"(__float_as_uint(a)), "r"(__float_as_uint(b)));
    return r;
}
__device__ __forceinline__ float2 unpk(unsigned long long v) {
    unsigned int lo, hi;
    asm("mov.b64 {%0, %1}, %2;" : "=r"(lo), "=r"(hi) : "l"(v));
    return make_float2(__uint_as_float(lo), __uint_as_float(hi));
}
__device__ __forceinline__ void ffma2(unsigned long long& d, unsigned long long a,
                                      unsigned long long b) {
    asm("fma.rn.f32x2 %0, %1, %2, %0;" : "+l"(d) : "l"(a), "l"(b));
}
__device__ __forceinline__ unsigned long long addp(unsigned long long a,
                                                   unsigned long long b) {
    unsigned long long r;
    asm("add.rn.f32x2 %0, %1, %2;" : "=l"(r) : "l"(a), "l"(b));
    return r;
}

// cos(2*pi*s/p): q may be off-by-one; r is then off by exactly one period,
// which cos() doesn't see. |2*pi*r*rcp| <= ~4*pi, fine for MUFU.
__device__ __forceinline__ float phase_cos(float sf, float pf, float rcp) {
    float q = floorf(sf * rcp);
    float r = fmaf(-q, pf, sf);          // exact (integers < 2^24)
    return __cosf(TWO_PI_F * (r * rcp));
}

} // namespace

// ---- packed weight scratch (position-invariant, rebuilt each launch) -------
__device__ float2 g_pk0[V * V];     // [j][i]: (charPT, 1/(i*V+j+2))
__device__ float2 g_pk1[D * D];     // [j][i]: (P1T, 1/(i*D+j+2))
__device__ float2 g_pk2[D * D];     // [j][i]: (P2T, 1/(i*D+j+2))
__device__ float2 g_mr [V * D];     // [j][i]: (M1T, R1T)
__device__ float  g_M2T[D * D];     // [j][i]

extern "C" __global__ void __launch_bounds__(256)
prep_weights(const float* __restrict__ charP, const float* __restrict__ M1,
             const float* __restrict__ R1,    const float* __restrict__ P1,
             const float* __restrict__ P2,    const float* __restrict__ M2)
{
    int t = blockIdx.x * blockDim.x + threadIdx.x;
    if (t < 4096) {                                   // charP 64x64
        int j = t >> 6, i = t & 63;
        g_pk0[t] = make_float2(charP[i * V + j], 1.0f / (float)(i * V + j + 2));
    } else if (t < 20480) {                           // P1 128x128
        int u = t - 4096; int j = u >> 7, i = u & 127;
        g_pk1[u] = make_float2(P1[i * D + j], 1.0f / (float)(i * D + j + 2));
    } else if (t < 36864) {                           // P2 128x128
        int u = t - 20480; int j = u >> 7, i = u & 127;
        g_pk2[u] = make_float2(P2[i * D + j], 1.0f / (float)(i * D + j + 2));
    } else if (t < 45056) {                           // M1,R1 64x128
        int u = t - 36864; int j = u >> 7, i = u & 127;
        g_mr[u] = make_float2(M1[i * V + j], R1[i * V + j]);
    } else if (t < 61440) {                           // M2 128x128
        int u = t - 45056; int j = u >> 7, i = u & 127;
        g_M2T[u] = M2[i * D + j];
    }
}

extern "C" __global__ void __launch_bounds__(128)
hier_kernel(const int* __restrict__ tokens, const int* __restrict__ positions,
            const float* __restrict__ emb,
            const float* __restrict__ g1, const float* __restrict__ b1v,
            const float* __restrict__ g2, const float* __restrict__ b2v,
            float* __restrict__ out)
{
    __shared__ Smem sm;

    const int sidx = blockIdx.x;
    const int tid  = (int)threadIdx.x;
    const int lane = tid & 31;
    const int wid  = tid >> 5;
    const float sf = (float)positions[sidx];

    // ---- gather char embeddings (pair layout) ----------------------------
    {
        int bA = tid >> 6;                 // 0 or 1
        int j  = tid & 63;
        int tkA = tokens[bA * S + sidx];
        int tkB = tokens[(bA + 2) * S + sidx];
        sm.xs2[0][j][bA] = emb[tkA * V + j];   // batches 0/1 -> pair 0
        sm.xs2[1][j][bA] = emb[tkB * V + j];   // batches 2/3 -> pair 1
    }
    __syncthreads();

    // ---- layer 0: h = (char_P .* phi64) @ x ------------------------------
    // thread: i = tid&63 owns output row i for pair (tid>>6)
    {
        const int i = tid & 63;
        const int p = tid >> 6;
        const float pbase = (float)(i * V + 2);
        unsigned long long acc = 0;
        #pragma unroll 8
        for (int j2 = 0; j2 < V / 2; ++j2) {
            ulonglong2 xx = *reinterpret_cast<const ulonglong2*>(&sm.xs2[p][2 * j2][0]);
            #pragma unroll
            for (int e = 0; e < 2; ++e) {
                int j = 2 * j2 + e;
                float2 wr = g_pk0[j * V + i];
                float a = wr.x * phase_cos(sf, pbase + (float)j, wr.y);
                ffma2(acc, dup2(a), e ? xx.y : xx.x);
            }
        }
        *reinterpret_cast<unsigned long long*>(&sm.hs2[p][i][0]) = acc;
    }
    __syncthreads();

    const int i = tid;   // output row for layers 1 & 2

    auto layernorm = [&](float (&tv)[B], const float* gg, const float* bb,
                         float (&ov)[B]) {
        float s1[B], s2[B];
        #pragma unroll
        for (int b = 0; b < B; ++b) { s1[b] = tv[b]; s2[b] = tv[b] * tv[b]; }
        #pragma unroll
        for (int o = 16; o; o >>= 1) {
            #pragma unroll
            for (int b = 0; b < B; ++b) {
                s1[b] += __shfl_xor_sync(0xffffffffu, s1[b], o);
                s2[b] += __shfl_xor_sync(0xffffffffu, s2[b], o);
            }
        }
        if (lane == 0) {
            #pragma unroll
            for (int b = 0; b < B; ++b) {
                sm.red[0][b][wid] = s1[b];
                sm.red[1][b][wid] = s2[b];
            }
        }
        __syncthreads();
        const float gi = gg[i], bi = bb[i];
        #pragma unroll
        for (int b = 0; b < B; ++b) {
            float su = sm.red[0][b][0] + sm.red[0][b][1] + sm.red[0][b][2] + sm.red[0][b][3];
            float sq = sm.red[1][b][0] + sm.red[1][b][1] + sm.red[1][b][2] + sm.red[1][b][3];
            float mu  = su * (1.0f / D);
            float var = fmaf(sq, 1.0f / D, -mu * mu);
            float rs  = rsqrtf(var + 1e-5f);
            ov[b] = fmaf((tv[b] - mu) * rs, gi, bi);
        }
    };

    // ---- layer 1: t1 = M1 @ h  and residual rv = R1 @ h (fused) ----------
    unsigned long long t1p[2] = {0ull, 0ull};
    unsigned long long rvp[2] = {0ull, 0ull};
    {
        #pragma unroll 8
        for (int j2 = 0; j2 < V / 2; ++j2) {
            ulonglong2 x0 = *reinterpret_cast<const ulonglong2*>(&sm.hs2[0][2 * j2][0]);
            ulonglong2 x1 = *reinterpret_cast<const ulonglong2*>(&sm.hs2[1][2 * j2][0]);
            #pragma unroll
            for (int e = 0; e < 2; ++e) {
                int j = 2 * j2 + e;
                float2 w = g_mr[j * D + i];
                unsigned long long xm0 = e ? x0.y : x0.x;
                unsigned long long xm1 = e ? x1.y : x1.x;
                unsigned long long wm = dup2(w.x), wr = dup2(w.y);
                ffma2(t1p[0], wm, xm0); ffma2(t1p[1], wm, xm1);
                ffma2(rvp[0], wr, xm0); ffma2(rvp[1], wr, xm1);
            }
        }
    }
    // layernorm(t1) -> ls2
    {
        float tv[B], nv[B];
        float2 a0 = unpk(t1p[0]), a1 = unpk(t1p[1]);
        tv[0] = a0.x; tv[1] = a0.y; tv[2] = a1.x; tv[3] = a1.y;
        layernorm(tv, g1, b1v, nv);
        *reinterpret_cast<unsigned long long*>(&sm.ls2[0][i][0]) = pk2(nv[0], nv[1]);
        *reinterpret_cast<unsigned long long*>(&sm.ls2[1][i][0]) = pk2(nv[2], nv[3]);
    }
    __syncthreads();

    const float pbase = (float)(i * D + 2);

    // ---- layer 1 pos_nk + residual --------------------------------------
    unsigned long long h1p[2] = {0ull, 0ull};
    {
        #pragma unroll 8
        for (int j2 = 0; j2 < D / 2; ++j2) {
            ulonglong2 x0 = *reinterpret_cast<const ulonglong2*>(&sm.ls2[0][2 * j2][0]);
            ulonglong2 x1 = *reinterpret_cast<const ulonglong2*>(&sm.ls2[1][2 * j2][0]);
            #pragma unroll
            for (int e = 0; e < 2; ++e) {
                int j = 2 * j2 + e;
                float2 wr = g_pk1[j * D + i];
                float a = wr.x * phase_cos(sf, pbase + (float)j, wr.y);
                unsigned long long ad = dup2(a);
                ffma2(h1p[0], ad, e ? x0.y : x0.x);
                ffma2(h1p[1], ad, e ? x1.y : x1.x);
            }
        }
        h1p[0] = addp(h1p[0], rvp[0]);
        h1p[1] = addp(h1p[1], rvp[1]);
        *reinterpret_cast<unsigned long long*>(&sm.h1s2[0][i][0]) = h1p[0];
        *reinterpret_cast<unsigned long long*>(&sm.h1s2[1][i][0]) = h1p[1];
    }
    __syncthreads();

    // ---- layer 2: t2 = M2 @ h1 -------------------------------------------
    unsigned long long t2p[2] = {0ull, 0ull};
    {
        #pragma unroll 8
        for (int j2 = 0; j2 < D / 2; ++j2) {
            ulonglong2 x0 = *reinterpret_cast<const ulonglong2*>(&sm.h1s2[0][2 * j2][0]);
            ulonglong2 x1 = *reinterpret_cast<const ulonglong2*>(&sm.h1s2[1][2 * j2][0]);
            #pragma unroll
            for (int e = 0; e < 2; ++e) {
                int j = 2 * j2 + e;
                unsigned long long wm = dup2(g_M2T[j * D + i]);
                ffma2(t2p[0], wm, e ? x0.y : x0.x);
                ffma2(t2p[1], wm, e ? x1.y : x1.x);
            }
        }
    }
    // layernorm(t2) -> ls2 (reuse)
    {
        float tv[B], nv[B];
        float2 a0 = unpk(t2p[0]), a1 = unpk(t2p[1]);
        tv[0] = a0.x; tv[1] = a0.y; tv[2] = a1.x; tv[3] = a1.y;
        layernorm(tv, g2, b2v, nv);
        __syncthreads();   // protect ls2 from layer-1 readers before overwrite
        *reinterpret_cast<unsigned long long*>(&sm.ls2[0][i][0]) = pk2(nv[0], nv[1]);
        *reinterpret_cast<unsigned long long*>(&sm.ls2[1][i][0]) = pk2(nv[2], nv[3]);
    }
    __syncthreads();

    // ---- layer 2 pos_nk + shared residual t2 ------------------------------
    unsigned long long ovp[2] = {0ull, 0ull};
    {
        #pragma unroll 8
        for (int j2 = 0; j2 < D / 2; ++j2) {
            ulonglong2 x0 = *reinterpret_cast<const ulonglong2*>(&sm.ls2[0][2 * j2][0]);
            ulonglong2 x1 = *reinterpret_cast<const ulonglong2*>(&sm.ls2[1][2 * j2][0]);
            #pragma unroll
            for (int e = 0; e < 2; ++e) {
                int j = 2 * j2 + e;
                float2 wr = g_pk2[j * D + i];
                float a = wr.x * phase_cos(sf, pbase + (float)j, wr.y);
                unsigned long long ad = dup2(a);
                ffma2(ovp[0], ad, e ? x0.y : x0.x);
                ffma2(ovp[1], ad, e ? x1.y : x1.x);
            }
        }
    }
    {
        float2 o0 = unpk(addp(ovp[0], t2p[0]));
        float2 o1 = unpk(addp(ovp[1], t2p[1]));
        out[(0 * S + sidx) * D + i] = o0.x;
        out[(1 * S + sidx) * D + i] = o0.y;
        out[(2 * S + sidx) * D + i] = o1.x;
        out[(3 * S + sidx) * D + i] = o1.y;
    }
}

extern "C" void kernel_launch(void* const* d_in, const int* in_sizes, int n_in,
                              void* d_out, int out_size) {
    const int*   tokens    = (const int*)d_in[0];
    const int*   positions = (const int*)d_in[1];
    const float* emb       = (const float*)d_in[2];
    const float* charP     = (const float*)d_in[3];
    const float* M1        = (const float*)d_in[4];
    const float* P1        = (const float*)d_in[5];
    const float* g1        = (const float*)d_in[6];
    const float* b1        = (const float*)d_in[7];
    const float* R1        = (const float*)d_in[8];
    const float* M2        = (const float*)d_in[9];
    const float* P2        = (const float*)d_in[10];
    const float* g2        = (const float*)d_in[11];
    const float* b2        = (const float*)d_in[12];
    float* out = (float*)d_out;

    prep_weights<<<(61440 + 255) / 256, 256>>>(charP, M1, R1, P1, P2, M2);

    hier_kernel<<<S, 128>>>(tokens, positions, emb, g1, b1, g2, b2, out);
}

// round 8
// speedup vs baseline: 3.0701x; 1.1572x over previous
#include <cuda_runtime.h>
#include <cstdint>

#define TWO_PI_F 6.28318530717958647692f

namespace {

constexpr int B = 4, S = 4096, V = 64, D = 128;

struct __align__(16) PosSmem {
    float xs2[2][V][2];    // [pair][j][half]  pair p = batches (2p, 2p+1)
    float hs2[2][V][2];
    float ls2[2][D][2];
    float h1s2[2][D][2];
    float red[2][B][2];    // [sum/sumsq][batch][warp-in-position]
};

// ---- f32x2 packed helpers --------------------------------------------------
__device__ __forceinline__ unsigned long long dup2(float a) {
    unsigned long long r; unsigned int u = __float_as_uint(a);
    asm("mov.b64 %0, {%1, %1};" : "=l"(r) : "r"(u));
    return r;
}
__device__ __forceinline__ unsigned long long pk2(float a, float b) {
    unsigned long long r;
    asm("mov.b64 %0, {%1, %2};" : "=l"(r) : "r"(__float_as_uint(a)), "r"(__float_as_uint(b)));
    return r;
}
__device__ __forceinline__ float2 unpk(unsigned long long v) {
    unsigned int lo, hi;
    asm("mov.b64 {%0, %1}, %2;" : "=r"(lo), "=r"(hi) : "l"(v));
    return make_float2(__uint_as_float(lo), __uint_as_float(hi));
}
__device__ __forceinline__ void ffma2(unsigned long long& d, unsigned long long a,
                                      unsigned long long b) {
    asm("fma.rn.f32x2 %0, %1, %2, %0;" : "+l"(d) : "l"(a), "l"(b));
}
__device__ __forceinline__ unsigned long long addp(unsigned long long a,
                                                   unsigned long long b) {
    unsigned long long r;
    asm("add.rn.f32x2 %0, %1, %2;" : "=l"(r) : "l"(a), "l"(b));
    return r;
}

// cos(2*pi*s/p): q may be off-by-one; r is then off by exactly one period,
// invisible to cos. |2*pi*r*rcp| <= ~4*pi, fine for MUFU.
__device__ __forceinline__ float phase_cos(float sf, float pf, float rcp) {
    float q = floorf(sf * rcp);
    float r = fmaf(-q, pf, sf);
    return __cosf(TWO_PI_F * (r * rcp));
}

} // namespace

// ---- packed weight scratch (position-invariant, rebuilt each launch) -------
__device__ float2 g_pk0[V * V];     // [j][i]: (charPT, 1/(i*V+j+2))
__device__ float2 g_pk1[D * D];     // [j][i]: (P1T, 1/(i*D+j+2))
__device__ float2 g_pk2[D * D];     // [j][i]: (P2T, 1/(i*D+j+2))
__device__ float2 g_mr [V * D];     // [j][i]: (M1T, R1T)
__device__ float  g_M2T[D * D];     // [j][i]

extern "C" __global__ void __launch_bounds__(256)
prep_weights(const float* __restrict__ charP, const float* __restrict__ M1,
             const float* __restrict__ R1,    const float* __restrict__ P1,
             const float* __restrict__ P2,    const float* __restrict__ M2)
{
    int t = blockIdx.x * blockDim.x + threadIdx.x;
    if (t < 4096) {                                   // charP 64x64
        int j = t >> 6, i = t & 63;
        g_pk0[t] = make_float2(charP[i * V + j], 1.0f / (float)(i * V + j + 2));
    } else if (t < 20480) {                           // P1 128x128
        int u = t - 4096; int j = u >> 7, i = u & 127;
        g_pk1[u] = make_float2(P1[i * D + j], 1.0f / (float)(i * D + j + 2));
    } else if (t < 36864) {                           // P2 128x128
        int u = t - 20480; int j = u >> 7, i = u & 127;
        g_pk2[u] = make_float2(P2[i * D + j], 1.0f / (float)(i * D + j + 2));
    } else if (t < 45056) {                           // M1,R1 64x128
        int u = t - 36864; int j = u >> 7, i = u & 127;
        g_mr[u] = make_float2(M1[i * V + j], R1[i * V + j]);
    } else if (t < 61440) {                           // M2 128x128
        int u = t - 45056; int j = u >> 7, i = u & 127;
        g_M2T[u] = M2[i * D + j];
    }
}

extern "C" __global__ void __launch_bounds__(128)
hier_kernel(const int* __restrict__ tokens, const int* __restrict__ positions,
            const float* __restrict__ emb,
            const float* __restrict__ g1, const float* __restrict__ b1v,
            const float* __restrict__ g2, const float* __restrict__ b2v,
            float* __restrict__ out)
{
    __shared__ PosSmem sm[2];

    const int tid  = (int)threadIdx.x;
    const int ph   = tid >> 6;            // position within CTA (0/1)
    const int t    = tid & 63;            // thread within position
    const int lane = tid & 31;
    const int wp   = (tid >> 5) & 1;      // warp within position
    const int sidx = blockIdx.x * 2 + ph;
    const float sf = (float)positions[sidx];
    PosSmem& PS = sm[ph];

    // ---- gather char embeddings ------------------------------------------
    {
        #pragma unroll
        for (int b = 0; b < B; ++b) {
            int tk = tokens[b * S + sidx];
            PS.xs2[b >> 1][t][b & 1] = emb[tk * V + t];
        }
    }
    __syncthreads();

    // ---- layer 0: h = (char_P .* phi64) @ x ------------------------------
    // thread t owns row i=t for BOTH pairs (phase computed once per (i,j)).
    {
        const int i = t;
        const float pbase = (float)(i * V + 2);
        unsigned long long acc0 = 0, acc1 = 0;
        #pragma unroll 8
        for (int j2 = 0; j2 < V / 2; ++j2) {
            ulonglong2 x0 = *reinterpret_cast<const ulonglong2*>(&PS.xs2[0][2 * j2][0]);
            ulonglong2 x1 = *reinterpret_cast<const ulonglong2*>(&PS.xs2[1][2 * j2][0]);
            #pragma unroll
            for (int e = 0; e < 2; ++e) {
                int j = 2 * j2 + e;
                float2 wr = g_pk0[j * V + i];
                float a = wr.x * phase_cos(sf, pbase + (float)j, wr.y);
                unsigned long long ad = dup2(a);
                ffma2(acc0, ad, e ? x0.y : x0.x);
                ffma2(acc1, ad, e ? x1.y : x1.x);
            }
        }
        *reinterpret_cast<unsigned long long*>(&PS.hs2[0][i][0]) = acc0;
        *reinterpret_cast<unsigned long long*>(&PS.hs2[1][i][0]) = acc1;
    }
    __syncthreads();

    const int i0 = t, i1 = t + 64;        // the two rows this thread owns

    // layernorm over 128 rows distributed 2/thread across 64 threads.
    auto layernorm2 = [&](float (&tv)[2][B], const float* gg, const float* bb,
                          float (&nv)[2][B]) {
        float s1[B], s2[B];
        #pragma unroll
        for (int b = 0; b < B; ++b) {
            s1[b] = tv[0][b] + tv[1][b];
            s2[b] = tv[0][b] * tv[0][b] + tv[1][b] * tv[1][b];
        }
        #pragma unroll
        for (int o = 16; o; o >>= 1) {
            #pragma unroll
            for (int b = 0; b < B; ++b) {
                s1[b] += __shfl_xor_sync(0xffffffffu, s1[b], o);
                s2[b] += __shfl_xor_sync(0xffffffffu, s2[b], o);
            }
        }
        if (lane == 0) {
            #pragma unroll
            for (int b = 0; b < B; ++b) {
                PS.red[0][b][wp] = s1[b];
                PS.red[1][b][wp] = s2[b];
            }
        }
        __syncthreads();
        const float gA = gg[i0], bA = bb[i0];
        const float gB = gg[i1], bB = bb[i1];
        #pragma unroll
        for (int b = 0; b < B; ++b) {
            float su = PS.red[0][b][0] + PS.red[0][b][1];
            float sq = PS.red[1][b][0] + PS.red[1][b][1];
            float mu  = su * (1.0f / D);
            float var = fmaf(sq, 1.0f / D, -mu * mu);
            float rs  = rsqrtf(var + 1e-5f);
            nv[0][b] = fmaf((tv[0][b] - mu) * rs, gA, bA);
            nv[1][b] = fmaf((tv[1][b] - mu) * rs, gB, bB);
        }
    };

    // ---- layer 1: t1 = M1 @ h and rv = R1 @ h (fused, 2 rows) ------------
    unsigned long long t1p[2][2] = {{0ull,0ull},{0ull,0ull}};
    unsigned long long rvp[2][2] = {{0ull,0ull},{0ull,0ull}};
    {
        #pragma unroll 8
        for (int j2 = 0; j2 < V / 2; ++j2) {
            ulonglong2 x0 = *reinterpret_cast<const ulonglong2*>(&PS.hs2[0][2 * j2][0]);
            ulonglong2 x1 = *reinterpret_cast<const ulonglong2*>(&PS.hs2[1][2 * j2][0]);
            #pragma unroll
            for (int e = 0; e < 2; ++e) {
                int j = 2 * j2 + e;
                float2 wA = g_mr[j * D + i0];
                float2 wB = g_mr[j * D + i1];
                unsigned long long xm0 = e ? x0.y : x0.x;
                unsigned long long xm1 = e ? x1.y : x1.x;
                unsigned long long mA = dup2(wA.x), rA = dup2(wA.y);
                unsigned long long mB = dup2(wB.x), rB = dup2(wB.y);
                ffma2(t1p[0][0], mA, xm0); ffma2(t1p[0][1], mA, xm1);
                ffma2(t1p[1][0], mB, xm0); ffma2(t1p[1][1], mB, xm1);
                ffma2(rvp[0][0], rA, xm0); ffma2(rvp[0][1], rA, xm1);
                ffma2(rvp[1][0], rB, xm0); ffma2(rvp[1][1], rB, xm1);
            }
        }
    }
    // layernorm(t1) -> ls2
    {
        float tv[2][B], nv[2][B];
        #pragma unroll
        for (int r = 0; r < 2; ++r) {
            float2 a0 = unpk(t1p[r][0]), a1 = unpk(t1p[r][1]);
            tv[r][0] = a0.x; tv[r][1] = a0.y; tv[r][2] = a1.x; tv[r][3] = a1.y;
        }
        layernorm2(tv, g1, b1v, nv);
        *reinterpret_cast<unsigned long long*>(&PS.ls2[0][i0][0]) = pk2(nv[0][0], nv[0][1]);
        *reinterpret_cast<unsigned long long*>(&PS.ls2[1][i0][0]) = pk2(nv[0][2], nv[0][3]);
        *reinterpret_cast<unsigned long long*>(&PS.ls2[0][i1][0]) = pk2(nv[1][0], nv[1][1]);
        *reinterpret_cast<unsigned long long*>(&PS.ls2[1][i1][0]) = pk2(nv[1][2], nv[1][3]);
    }
    __syncthreads();

    const float pb0 = (float)(i0 * D + 2);
    const float pb1 = (float)(i1 * D + 2);

    // ---- layer 1 pos_nk + residual ---------------------------------------
    unsigned long long h1p[2][2] = {{0ull,0ull},{0ull,0ull}};
    {
        #pragma unroll 4
        for (int j2 = 0; j2 < D / 2; ++j2) {
            ulonglong2 x0 = *reinterpret_cast<const ulonglong2*>(&PS.ls2[0][2 * j2][0]);
            ulonglong2 x1 = *reinterpret_cast<const ulonglong2*>(&PS.ls2[1][2 * j2][0]);
            #pragma unroll
            for (int e = 0; e < 2; ++e) {
                int j = 2 * j2 + e;
                float2 wA = g_pk1[j * D + i0];
                float2 wB = g_pk1[j * D + i1];
                float aA = wA.x * phase_cos(sf, pb0 + (float)j, wA.y);
                float aB = wB.x * phase_cos(sf, pb1 + (float)j, wB.y);
                unsigned long long adA = dup2(aA), adB = dup2(aB);
                unsigned long long xm0 = e ? x0.y : x0.x;
                unsigned long long xm1 = e ? x1.y : x1.x;
                ffma2(h1p[0][0], adA, xm0); ffma2(h1p[0][1], adA, xm1);
                ffma2(h1p[1][0], adB, xm0); ffma2(h1p[1][1], adB, xm1);
            }
        }
        #pragma unroll
        for (int r = 0; r < 2; ++r) {
            h1p[r][0] = addp(h1p[r][0], rvp[r][0]);
            h1p[r][1] = addp(h1p[r][1], rvp[r][1]);
        }
        *reinterpret_cast<unsigned long long*>(&PS.h1s2[0][i0][0]) = h1p[0][0];
        *reinterpret_cast<unsigned long long*>(&PS.h1s2[1][i0][0]) = h1p[0][1];
        *reinterpret_cast<unsigned long long*>(&PS.h1s2[0][i1][0]) = h1p[1][0];
        *reinterpret_cast<unsigned long long*>(&PS.h1s2[1][i1][0]) = h1p[1][1];
    }
    __syncthreads();

    // ---- layer 2: t2 = M2 @ h1 -------------------------------------------
    unsigned long long t2p[2][2] = {{0ull,0ull},{0ull,0ull}};
    {
        #pragma unroll 8
        for (int j2 = 0; j2 < D / 2; ++j2) {
            ulonglong2 x0 = *reinterpret_cast<const ulonglong2*>(&PS.h1s2[0][2 * j2][0]);
            ulonglong2 x1 = *reinterpret_cast<const ulonglong2*>(&PS.h1s2[1][2 * j2][0]);
            #pragma unroll
            for (int e = 0; e < 2; ++e) {
                int j = 2 * j2 + e;
                unsigned long long mA = dup2(g_M2T[j * D + i0]);
                unsigned long long mB = dup2(g_M2T[j * D + i1]);
                unsigned long long xm0 = e ? x0.y : x0.x;
                unsigned long long xm1 = e ? x1.y : x1.x;
                ffma2(t2p[0][0], mA, xm0); ffma2(t2p[0][1], mA, xm1);
                ffma2(t2p[1][0], mB, xm0); ffma2(t2p[1][1], mB, xm1);
            }
        }
    }
    // layernorm(t2) -> ls2 (safe: last ls2 readers finished before h1 sync)
    {
        float tv[2][B], nv[2][B];
        #pragma unroll
        for (int r = 0; r < 2; ++r) {
            float2 a0 = unpk(t2p[r][0]), a1 = unpk(t2p[r][1]);
            tv[r][0] = a0.x; tv[r][1] = a0.y; tv[r][2] = a1.x; tv[r][3] = a1.y;
        }
        layernorm2(tv, g2, b2v, nv);
        __syncthreads();
        *reinterpret_cast<unsigned long long*>(&PS.ls2[0][i0][0]) = pk2(nv[0][0], nv[0][1]);
        *reinterpret_cast<unsigned long long*>(&PS.ls2[1][i0][0]) = pk2(nv[0][2], nv[0][3]);
        *reinterpret_cast<unsigned long long*>(&PS.ls2[0][i1][0]) = pk2(nv[1][0], nv[1][1]);
        *reinterpret_cast<unsigned long long*>(&PS.ls2[1][i1][0]) = pk2(nv[1][2], nv[1][3]);
    }
    __syncthreads();

    // ---- layer 2 pos_nk + shared residual t2 ------------------------------
    unsigned long long ovp[2][2] = {{0ull,0ull},{0ull,0ull}};
    {
        #pragma unroll 4
        for (int j2 = 0; j2 < D / 2; ++j2) {
            ulonglong2 x0 = *reinterpret_cast<const ulonglong2*>(&PS.ls2[0][2 * j2][0]);
            ulonglong2 x1 = *reinterpret_cast<const ulonglong2*>(&PS.ls2[1][2 * j2][0]);
            #pragma unroll
            for (int e = 0; e < 2; ++e) {
                int j = 2 * j2 + e;
                float2 wA = g_pk2[j * D + i0];
                float2 wB = g_pk2[j * D + i1];
                float aA = wA.x * phase_cos(sf, pb0 + (float)j, wA.y);
                float aB = wB.x * phase_cos(sf, pb1 + (float)j, wB.y);
                unsigned long long adA = dup2(aA), adB = dup2(aB);
                unsigned long long xm0 = e ? x0.y : x0.x;
                unsigned long long xm1 = e ? x1.y : x1.x;
                ffma2(ovp[0][0], adA, xm0); ffma2(ovp[0][1], adA, xm1);
                ffma2(ovp[1][0], adB, xm0); ffma2(ovp[1][1], adB, xm1);
            }
        }
    }
    {
        float2 o00 = unpk(addp(ovp[0][0], t2p[0][0]));   // row i0, batches 0/1
        float2 o01 = unpk(addp(ovp[0][1], t2p[0][1]));   // row i0, batches 2/3
        float2 o10 = unpk(addp(ovp[1][0], t2p[1][0]));   // row i1, batches 0/1
        float2 o11 = unpk(addp(ovp[1][1], t2p[1][1]));   // row i1, batches 2/3
        out[(0 * S + sidx) * D + i0] = o00.x;
        out[(1 * S + sidx) * D + i0] = o00.y;
        out[(2 * S + sidx) * D + i0] = o01.x;
        out[(3 * S + sidx) * D + i0] = o01.y;
        out[(0 * S + sidx) * D + i1] = o10.x;
        out[(1 * S + sidx) * D + i1] = o10.y;
        out[(2 * S + sidx) * D + i1] = o11.x;
        out[(3 * S + sidx) * D + i1] = o11.y;
    }
}

extern "C" void kernel_launch(void* const* d_in, const int* in_sizes, int n_in,
                              void* d_out, int out_size) {
    const int*   tokens    = (const int*)d_in[0];
    const int*   positions = (const int*)d_in[1];
    const float* emb       = (const float*)d_in[2];
    const float* charP     = (const float*)d_in[3];
    const float* M1        = (const float*)d_in[4];
    const float* P1        = (const float*)d_in[5];
    const float* g1        = (const float*)d_in[6];
    const float* b1        = (const float*)d_in[7];
    const float* R1        = (const float*)d_in[8];
    const float* M2        = (const float*)d_in[9];
    const float* P2        = (const float*)d_in[10];
    const float* g2        = (const float*)d_in[11];
    const float* b2        = (const float*)d_in[12];
    float* out = (float*)d_out;

    prep_weights<<<(61440 + 255) / 256, 256>>>(charP, M1, R1, P1, P2, M2);

    hier_kernel<<<S / 2, 128>>>(tokens, positions, emb, g1, b1, g2, b2, out);
}